// round 10
// baseline (speedup 1.0000x reference)
#include <cuda_runtime.h>
#include <cstdint>

// Problem constants: B=2, C=256, H=W=64 -> P=Q=4096, N=4, RADIUS=4 -> K2=81, 4 levels.
#define PQ   4096
#define KC   256
#define PYR  5440      // per-(b,p) pyramid floats: 4096 + 1024 + 256 + 64
#define PAD_A 264      // 256+8 : stride ≡ 8 (mod 32) -> conflict-free frag loads
#define PAD_B 136      // 128+8
#define SA_FLOATS (2 * 16 * PAD_A)             // 8448
#define SB_FLOATS (2 * 16 * PAD_B)             // 4352
#define SMEM_BYTES ((SA_FLOATS + SB_FLOATS) * 4)   // 51200 > 48K -> needs attribute

// Scratch pyramid: 2 * 4096 * 5440 floats = ~178 MB (device global; no runtime alloc).
__device__ float g_pyr[(size_t)2 * PQ * PYR];

__device__ __forceinline__ float to_tf32(float x) {
    uint32_t u;
    asm("cvt.rna.tf32.f32 %0, %1;" : "=r"(u) : "f"(x));
    return __uint_as_float(u);
}

__device__ __forceinline__ void mma_tf32(float d[4], const uint32_t a[4], const uint32_t b[2]) {
    asm volatile(
        "mma.sync.aligned.m16n8k8.row.col.f32.tf32.tf32.f32 "
        "{%0,%1,%2,%3}, {%4,%5,%6,%7}, {%8,%9}, {%0,%1,%2,%3};\n"
        : "+f"(d[0]), "+f"(d[1]), "+f"(d[2]), "+f"(d[3])
        : "r"(a[0]), "r"(a[1]), "r"(a[2]), "r"(a[3]), "r"(b[0]), "r"(b[1]));
}

// ---------------------------------------------------------------------------
// Stage 1: corr[b,p,q] = (1/16) * sum_c f1[b,c,p] * f2[b,c,q]
// Block tile 256(m) x 128(n), 8 warps (4x2 of 64x64 warp tiles), k-tile 16,
// double-buffered smem (all dynamic: sA then sB) with register prefetch.
// Epilogue also computes pyramid level-1 (2x2 pooling): block n-span = one
// full qy pair x all qx, so pooling closes within the block.
// ---------------------------------------------------------------------------
__global__ __launch_bounds__(256) void gemm_corr(const float* __restrict__ f1,
                                                 const float* __restrict__ f2) {
    extern __shared__ float smem_dyn[];
    float* sA = smem_dyn;                      // [2][16][PAD_A]
    float* sB = smem_dyn + SA_FLOATS;          // [2][16][PAD_B]

    const int bz = blockIdx.z;
    const float* A  = f1 + (size_t)bz * KC * PQ;
    const float* Bg = f2 + (size_t)bz * KC * PQ;
    float* C = g_pyr + (size_t)bz * PQ * PYR;

    const int m0 = blockIdx.y * 256;
    const int n0 = blockIdx.x * 128;
    const int tid  = threadIdx.x;
    const int warp = tid >> 5, lane = tid & 31;
    const int wn = (warp & 1) * 64;            // n-halves: qy even / odd row
    const int wm = (warp >> 1) * 64;           // 4 m-warps
    const int tg = lane >> 2, t4 = lane & 3;

    float acc[4][8][4];
#pragma unroll
    for (int i = 0; i < 4; i++)
#pragma unroll
        for (int j = 0; j < 8; j++)
#pragma unroll
            for (int q = 0; q < 4; q++) acc[i][j][q] = 0.f;

    // Loader mapping. A tile: 16 rows x 256 floats = 1024 float4, 4/thread.
    // B tile: 16 rows x 128 floats = 512 float4, 2/thread. Fully coalesced.
    int akr[4], akc[4], bkr[2], bkc[2];
#pragma unroll
    for (int r = 0; r < 4; r++) {
        int lin = r * 256 + tid;
        akr[r] = lin >> 6;
        akc[r] = (lin & 63) * 4;
    }
#pragma unroll
    for (int r = 0; r < 2; r++) {
        int lin = r * 256 + tid;
        bkr[r] = lin >> 5;
        bkc[r] = (lin & 31) * 4;
    }

    float4 pa[4], pb[2];
#pragma unroll
    for (int r = 0; r < 4; r++)
        pa[r] = *(const float4*)(A + (size_t)akr[r] * PQ + m0 + akc[r]);
#pragma unroll
    for (int r = 0; r < 2; r++)
        pb[r] = *(const float4*)(Bg + (size_t)bkr[r] * PQ + n0 + bkc[r]);
#pragma unroll
    for (int r = 0; r < 4; r++) {
        float4 a4 = pa[r];
        *(float4*)&sA[akr[r] * PAD_A + akc[r]] =
            make_float4(to_tf32(a4.x), to_tf32(a4.y), to_tf32(a4.z), to_tf32(a4.w));
    }
#pragma unroll
    for (int r = 0; r < 2; r++) {
        float4 b4 = pb[r];
        *(float4*)&sB[bkr[r] * PAD_B + bkc[r]] =
            make_float4(to_tf32(b4.x), to_tf32(b4.y), to_tf32(b4.z), to_tf32(b4.w));
    }
    __syncthreads();

    for (int kt = 0; kt < 16; kt++) {
        const int buf = kt & 1;
        const float* sAb = sA + buf * (16 * PAD_A);
        const float* sBb = sB + buf * (16 * PAD_B);
        if (kt < 15) {
            const int kb = (kt + 1) * 16;
#pragma unroll
            for (int r = 0; r < 4; r++)
                pa[r] = *(const float4*)(A + (size_t)(kb + akr[r]) * PQ + m0 + akc[r]);
#pragma unroll
            for (int r = 0; r < 2; r++)
                pb[r] = *(const float4*)(Bg + (size_t)(kb + bkr[r]) * PQ + n0 + bkc[r]);
        }
#pragma unroll
        for (int kk = 0; kk < 16; kk += 8) {
            uint32_t af[4][4], bf[8][2];
#pragma unroll
            for (int mt = 0; mt < 4; mt++) {
                const int mb = wm + mt * 16 + tg;
                af[mt][0] = __float_as_uint(sAb[(kk + t4) * PAD_A + mb]);
                af[mt][1] = __float_as_uint(sAb[(kk + t4) * PAD_A + mb + 8]);
                af[mt][2] = __float_as_uint(sAb[(kk + t4 + 4) * PAD_A + mb]);
                af[mt][3] = __float_as_uint(sAb[(kk + t4 + 4) * PAD_A + mb + 8]);
            }
#pragma unroll
            for (int nt = 0; nt < 8; nt++) {
                const int nb = wn + nt * 8 + tg;
                bf[nt][0] = __float_as_uint(sBb[(kk + t4) * PAD_B + nb]);
                bf[nt][1] = __float_as_uint(sBb[(kk + t4 + 4) * PAD_B + nb]);
            }
#pragma unroll
            for (int mt = 0; mt < 4; mt++)
#pragma unroll
                for (int nt = 0; nt < 8; nt++)
                    mma_tf32(acc[mt][nt], af[mt], bf[nt]);
        }
        if (kt < 15) {
            const int nb2 = buf ^ 1;
            float* sAn = sA + nb2 * (16 * PAD_A);
            float* sBn = sB + nb2 * (16 * PAD_B);
#pragma unroll
            for (int r = 0; r < 4; r++) {
                float4 a4 = pa[r];
                *(float4*)&sAn[akr[r] * PAD_A + akc[r]] =
                    make_float4(to_tf32(a4.x), to_tf32(a4.y), to_tf32(a4.z), to_tf32(a4.w));
            }
#pragma unroll
            for (int r = 0; r < 2; r++) {
                float4 b4 = pb[r];
                *(float4*)&sBn[bkr[r] * PAD_B + bkc[r]] =
                    make_float4(to_tf32(b4.x), to_tf32(b4.y), to_tf32(b4.z), to_tf32(b4.w));
            }
            __syncthreads();
        }
    }

    // ---------------- Epilogue: level-0 store + fused level-1 pooling -------
    const float sc = 0.0625f;                  // 1/sqrt(256)
    __syncthreads();                           // done reading smem: reuse as sP
    float* sP = sA;                            // [256][33] = 8448 floats

    if (wn == 64) {                            // qy-odd warps deposit h-sums
#pragma unroll
        for (int mt = 0; mt < 4; mt++) {
            const int r = wm + mt * 16 + tg;
#pragma unroll
            for (int nt = 0; nt < 8; nt++) {
                const int lx = nt * 4 + t4;
                sP[r * 33 + lx]       = acc[mt][nt][0] + acc[mt][nt][1];
                sP[(r + 8) * 33 + lx] = acc[mt][nt][2] + acc[mt][nt][3];
            }
        }
    }

    // Level-0 writes (all warps, overlaps with the smem exchange).
#pragma unroll
    for (int mt = 0; mt < 4; mt++) {
        const int m = m0 + wm + mt * 16 + tg;
#pragma unroll
        for (int nt = 0; nt < 8; nt++) {
            const int nc = n0 + wn + nt * 8 + t4 * 2;
            *(float2*)(C + (size_t)m * PYR + nc) =
                make_float2(acc[mt][nt][0] * sc, acc[mt][nt][1] * sc);
            *(float2*)(C + (size_t)(m + 8) * PYR + nc) =
                make_float2(acc[mt][nt][2] * sc, acc[mt][nt][3] * sc);
        }
    }
    __syncthreads();

    if (wn == 0) {                             // combine qy pair -> l1 values
        const float q = 0.25f * sc;
#pragma unroll
        for (int mt = 0; mt < 4; mt++) {
            const int r = wm + mt * 16 + tg;
#pragma unroll
            for (int nt = 0; nt < 8; nt++) {
                const int lx = nt * 4 + t4;
                sP[r * 33 + lx] =
                    q * (acc[mt][nt][0] + acc[mt][nt][1] + sP[r * 33 + lx]);
                sP[(r + 8) * 33 + lx] =
                    q * (acc[mt][nt][2] + acc[mt][nt][3] + sP[(r + 8) * 33 + lx]);
            }
        }
    }
    __syncthreads();

    // Coalesced level-1 store: warp w owns rows w*32..w*32+31.
    {
        float* l1 = C + 4096 + blockIdx.x * 32;    // ly = blockIdx.x
#pragma unroll
        for (int rr = 0; rr < 32; rr++) {
            const int r = warp * 32 + rr;
            l1[(size_t)(m0 + r) * PYR + lane] = sP[r * 33 + lane];
        }
    }
}

// ---------------------------------------------------------------------------
// Stage 2: levels 2,3 from level 1. One block per (b,p), 256 threads.
// ---------------------------------------------------------------------------
__global__ __launch_bounds__(256) void pool23_kernel() {
    const size_t bp = blockIdx.x;
    float* base = g_pyr + bp * PYR;
    const float* l1 = base + 4096;
    float* l2 = base + 5120;
    float* l3 = base + 5376;

    __shared__ float s1[1024];
    __shared__ float s2[256];
    const int t = threadIdx.x;

    ((float4*)s1)[t] = ((const float4*)l1)[t];
    __syncthreads();
    {
        int y = t >> 4, x = t & 15;
        const float* r = s1 + y * 64 + x * 2;      // (2y)*32 + 2x
        float v = 0.25f * (r[0] + r[1] + r[32] + r[33]);
        s2[t] = v;
        l2[t] = v;
    }
    __syncthreads();
    if (t < 64) {
        int y = t >> 3, x = t & 7;
        const float* r = s2 + y * 32 + x * 2;      // (2y)*16 + 2x
        l3[t] = 0.25f * (r[0] + r[1] + r[16] + r[17]);
    }
}

// ---------------------------------------------------------------------------
// Stage 3: one thread per output element. Faithful to the reference's delta
// swap: x gets d[k/9], y gets d[k%9]. Output flat (B,N,P,324)==(B,N*C,H,W).
// ---------------------------------------------------------------------------
__global__ __launch_bounds__(256) void gather_kernel(const float* __restrict__ coords,
                                                     float* __restrict__ out) {
    const int idx = blockIdx.x * 256 + threadIdx.x;    // exact: no bounds needed
    const int c   = idx % 324;
    const int bnp = idx / 324;
    const int p  = bnp & 4095;
    const int bn = bnp >> 12;
    const int b  = bn >> 2;

    const float cx = coords[((size_t)bn * 2)     * PQ + p];
    const float cy = coords[((size_t)bn * 2 + 1) * PQ + p];

    const float* pyr = g_pyr + ((((size_t)b << 12) | (size_t)p) * PYR);

    const int l = c / 81;
    const int k = c - l * 81;
    const int dim  = 64 >> l;
    const float inv = 1.0f / (float)(1 << l);
    const int loff = (l == 0) ? 0 : (l == 1) ? 4096 : (l == 2) ? 5120 : 5376;
    const float* lv = pyr + loff;

    const int ki = k / 9;
    const float x = cx * inv + (float)(ki - 4);            // off_x = d[k/9]
    const float y = cy * inv + (float)(k - ki * 9 - 4);    // off_y = d[k%9]

    const float x0f = floorf(x), y0f = floorf(y);
    const int x0 = (int)x0f, y0 = (int)y0f;
    const float fx = x - x0f, fy = y - y0f;

    const bool xv0 = (x0 >= 0) && (x0 < dim);
    const bool xv1 = (x0 >= -1) && (x0 < dim - 1);
    const bool yv0 = (y0 >= 0) && (y0 < dim);
    const bool yv1 = (y0 >= -1) && (y0 < dim - 1);

    float v00 = 0.f, v01 = 0.f, v10 = 0.f, v11 = 0.f;
    const float* row0 = lv + y0 * dim;
    if (yv0) {
        if (xv0) v00 = row0[x0];
        if (xv1) v01 = row0[x0 + 1];
    }
    if (yv1) {
        if (xv0) v10 = row0[dim + x0];
        if (xv1) v11 = row0[dim + x0 + 1];
    }
    out[idx] = (1.f - fy) * ((1.f - fx) * v00 + fx * v01)
             + fy         * ((1.f - fx) * v10 + fx * v11);
}

extern "C" void kernel_launch(void* const* d_in, const int* in_sizes, int n_in,
                              void* d_out, int out_size) {
    const float* f1     = (const float*)d_in[0];   // (2, 256, 64, 64)
    const float* f2     = (const float*)d_in[1];   // (2, 256, 64, 64)
    const float* coords = (const float*)d_in[2];   // (2, 4, 2, 64, 64)
    float* out = (float*)d_out;                    // (2, 4*324, 64, 64)

    // 51200 B dynamic smem > 48K default: opt in. Not a stream op (executes
    // immediately, not captured), idempotent and deterministic on every call.
    cudaFuncSetAttribute(gemm_corr, cudaFuncAttributeMaxDynamicSharedMemorySize,
                         SMEM_BYTES);

    dim3 g(32, 16, 2);                             // n-tiles, m-tiles, batch
    gemm_corr<<<g, 256, SMEM_BYTES>>>(f1, f2);
    pool23_kernel<<<2 * PQ, 256>>>();
    gather_kernel<<<(2 * 4 * PQ * 324) / 256, 256>>>(coords, out);
}

// round 16
// speedup vs baseline: 1.0751x; 1.0751x over previous
#include <cuda_runtime.h>
#include <cstdint>

// Problem constants: B=2, C=256, H=W=64 -> P=Q=4096, N=4, RADIUS=4 -> K2=81, 4 levels.
#define PQ   4096
#define KC   256
#define PYR  5440      // per-(b,p) pyramid floats: 4096 + 1024 + 256 + 64
#define PAD  136       // smem row stride (floats): 128 + 8 -> conflict-free frag loads

// Scratch pyramid: 2 * 4096 * 5440 floats = ~178 MB (device global; no runtime alloc).
__device__ float g_pyr[(size_t)2 * PQ * PYR];

__device__ __forceinline__ float to_tf32(float x) {
    uint32_t u;
    asm("cvt.rna.tf32.f32 %0, %1;" : "=r"(u) : "f"(x));
    return __uint_as_float(u);
}

__device__ __forceinline__ void mma_tf32(float d[4], const uint32_t a[4], const uint32_t b[2]) {
    asm volatile(
        "mma.sync.aligned.m16n8k8.row.col.f32.tf32.tf32.f32 "
        "{%0,%1,%2,%3}, {%4,%5,%6,%7}, {%8,%9}, {%0,%1,%2,%3};\n"
        : "+f"(d[0]), "+f"(d[1]), "+f"(d[2]), "+f"(d[3])
        : "r"(a[0]), "r"(a[1]), "r"(a[2]), "r"(a[3]), "r"(b[0]), "r"(b[1]));
}

// ---------------------------------------------------------------------------
// Stage 1: corr[b,p,q] = (1/16) * sum_c f1[b,c,p] * f2[b,c,q]
// EXACT R1 mainloop (measured best: 2 CTAs/SM, tensor 42.8%): block tile
// 128x128, 4 warps (2x2 of 64x64), k-tile 16, double-buffered smem with
// register prefetch. Epilogue fuses pyramid level-1 (2x2 pooling) —
// the 128-wide n-span is one full qy pair x all qx, so pooling closes
// within the block. 35 KB static smem (no opt-in attribute needed).
// ---------------------------------------------------------------------------
__global__ __launch_bounds__(128) void gemm_corr(const float* __restrict__ f1,
                                                 const float* __restrict__ f2) {
    __shared__ float sA[2][16][PAD];
    __shared__ float sB[2][16][PAD];

    const int bz = blockIdx.z;
    const float* A  = f1 + (size_t)bz * KC * PQ;
    const float* Bg = f2 + (size_t)bz * KC * PQ;
    float* C = g_pyr + (size_t)bz * PQ * PYR;

    const int m0 = blockIdx.y * 128;
    const int n0 = blockIdx.x * 128;
    const int tid  = threadIdx.x;
    const int warp = tid >> 5, lane = tid & 31;
    const int wm = (warp & 1) * 64;            // 2 m-halves
    const int wn = (warp >> 1) * 64;           // n-halves: qy even / odd row
    const int tg = lane >> 2, t4 = lane & 3;

    float acc[4][8][4];
#pragma unroll
    for (int i = 0; i < 4; i++)
#pragma unroll
        for (int j = 0; j < 8; j++)
#pragma unroll
            for (int q = 0; q < 4; q++) acc[i][j][q] = 0.f;

    // Global loader mapping: 16 rows x 128 floats per tile = 512 float4,
    // 128 threads x 4 float4 each, fully coalesced.
    int lk[4], lc[4];
#pragma unroll
    for (int r = 0; r < 4; r++) {
        int lin = r * 128 + tid;
        lk[r] = lin >> 5;
        lc[r] = (lin & 31) * 4;
    }

    float4 pa[4], pb[4];
#pragma unroll
    for (int r = 0; r < 4; r++) {
        pa[r] = *(const float4*)(A  + (size_t)lk[r] * PQ + m0 + lc[r]);
        pb[r] = *(const float4*)(Bg + (size_t)lk[r] * PQ + n0 + lc[r]);
    }
#pragma unroll
    for (int r = 0; r < 4; r++) {
        float4 a4 = pa[r], b4 = pb[r];
        *(float4*)&sA[0][lk[r]][lc[r]] =
            make_float4(to_tf32(a4.x), to_tf32(a4.y), to_tf32(a4.z), to_tf32(a4.w));
        *(float4*)&sB[0][lk[r]][lc[r]] =
            make_float4(to_tf32(b4.x), to_tf32(b4.y), to_tf32(b4.z), to_tf32(b4.w));
    }
    __syncthreads();

    for (int kt = 0; kt < 16; kt++) {
        const int buf = kt & 1;
        if (kt < 15) {
            const int kb = (kt + 1) * 16;
#pragma unroll
            for (int r = 0; r < 4; r++) {
                pa[r] = *(const float4*)(A  + (size_t)(kb + lk[r]) * PQ + m0 + lc[r]);
                pb[r] = *(const float4*)(Bg + (size_t)(kb + lk[r]) * PQ + n0 + lc[r]);
            }
        }
#pragma unroll
        for (int kk = 0; kk < 16; kk += 8) {
            uint32_t af[4][4], bf[8][2];
#pragma unroll
            for (int mt = 0; mt < 4; mt++) {
                const int mb = wm + mt * 16 + tg;
                af[mt][0] = __float_as_uint(sA[buf][kk + t4][mb]);
                af[mt][1] = __float_as_uint(sA[buf][kk + t4][mb + 8]);
                af[mt][2] = __float_as_uint(sA[buf][kk + t4 + 4][mb]);
                af[mt][3] = __float_as_uint(sA[buf][kk + t4 + 4][mb + 8]);
            }
#pragma unroll
            for (int nt = 0; nt < 8; nt++) {
                const int nb = wn + nt * 8 + tg;
                bf[nt][0] = __float_as_uint(sB[buf][kk + t4][nb]);
                bf[nt][1] = __float_as_uint(sB[buf][kk + t4 + 4][nb]);
            }
#pragma unroll
            for (int mt = 0; mt < 4; mt++)
#pragma unroll
                for (int nt = 0; nt < 8; nt++)
                    mma_tf32(acc[mt][nt], af[mt], bf[nt]);
        }
        if (kt < 15) {
            const int nb2 = buf ^ 1;
#pragma unroll
            for (int r = 0; r < 4; r++) {
                float4 a4 = pa[r], b4 = pb[r];
                *(float4*)&sA[nb2][lk[r]][lc[r]] =
                    make_float4(to_tf32(a4.x), to_tf32(a4.y), to_tf32(a4.z), to_tf32(a4.w));
                *(float4*)&sB[nb2][lk[r]][lc[r]] =
                    make_float4(to_tf32(b4.x), to_tf32(b4.y), to_tf32(b4.z), to_tf32(b4.w));
            }
            __syncthreads();
        }
    }

    // ---------------- Epilogue: level-0 store + fused level-1 pooling -------
    // n-span 128 = qy rows {2bx, 2bx+1} x qx 0..63. wn=0 warps own qy-even,
    // wn=64 warps own qy-odd. Horizontal pair = within-lane acc[0]+acc[1]
    // (cols nc, nc+1). Vertical pair exchanged through sA (reused as sP).
    const float sc = 0.0625f;                  // 1/sqrt(256)
    __syncthreads();                           // all warps done reading smem
    float* sP = &sA[0][0][0];                  // [128][33] = 4224 <= 4352 floats

    if (wn == 64) {                            // qy-odd warps deposit h-sums
#pragma unroll
        for (int mt = 0; mt < 4; mt++) {
            const int r = wm + mt * 16 + tg;
#pragma unroll
            for (int nt = 0; nt < 8; nt++) {
                const int lx = nt * 4 + t4;
                sP[r * 33 + lx]       = acc[mt][nt][0] + acc[mt][nt][1];
                sP[(r + 8) * 33 + lx] = acc[mt][nt][2] + acc[mt][nt][3];
            }
        }
    }

    // Level-0 writes (all warps, overlaps with the smem exchange).
#pragma unroll
    for (int mt = 0; mt < 4; mt++) {
        const int m = m0 + wm + mt * 16 + tg;
#pragma unroll
        for (int nt = 0; nt < 8; nt++) {
            const int nc = n0 + wn + nt * 8 + t4 * 2;
            *(float2*)(C + (size_t)m * PYR + nc) =
                make_float2(acc[mt][nt][0] * sc, acc[mt][nt][1] * sc);
            *(float2*)(C + (size_t)(m + 8) * PYR + nc) =
                make_float2(acc[mt][nt][2] * sc, acc[mt][nt][3] * sc);
        }
    }
    __syncthreads();

    if (wn == 0) {                             // combine qy pair -> l1 values
        const float q = 0.25f * sc;
#pragma unroll
        for (int mt = 0; mt < 4; mt++) {
            const int r = wm + mt * 16 + tg;
#pragma unroll
            for (int nt = 0; nt < 8; nt++) {
                const int lx = nt * 4 + t4;
                sP[r * 33 + lx] =
                    q * (acc[mt][nt][0] + acc[mt][nt][1] + sP[r * 33 + lx]);
                sP[(r + 8) * 33 + lx] =
                    q * (acc[mt][nt][2] + acc[mt][nt][3] + sP[(r + 8) * 33 + lx]);
            }
        }
    }
    __syncthreads();

    // Coalesced level-1 store: warp w owns rows w*32..w*32+31 (128 rows).
    {
        float* l1 = C + 4096 + blockIdx.x * 32;    // ly = blockIdx.x
#pragma unroll
        for (int rr = 0; rr < 32; rr++) {
            const int r = warp * 32 + rr;
            l1[(size_t)(m0 + r) * PYR + lane] = sP[r * 33 + lane];
        }
    }
}

// ---------------------------------------------------------------------------
// Stage 2: levels 2,3 from level 1. One block per (b,p), 256 threads.
// ---------------------------------------------------------------------------
__global__ __launch_bounds__(256) void pool23_kernel() {
    const size_t bp = blockIdx.x;
    float* base = g_pyr + bp * PYR;
    const float* l1 = base + 4096;
    float* l2 = base + 5120;
    float* l3 = base + 5376;

    __shared__ float s1[1024];
    __shared__ float s2[256];
    const int t = threadIdx.x;

    ((float4*)s1)[t] = ((const float4*)l1)[t];
    __syncthreads();
    {
        int y = t >> 4, x = t & 15;
        const float* r = s1 + y * 64 + x * 2;      // (2y)*32 + 2x
        float v = 0.25f * (r[0] + r[1] + r[32] + r[33]);
        s2[t] = v;
        l2[t] = v;
    }
    __syncthreads();
    if (t < 64) {
        int y = t >> 3, x = t & 7;
        const float* r = s2 + y * 32 + x * 2;      // (2y)*16 + 2x
        l3[t] = 0.25f * (r[0] + r[1] + r[16] + r[17]);
    }
}

// ---------------------------------------------------------------------------
// Stage 3: one thread per output element. Faithful to the reference's delta
// swap: x gets d[k/9], y gets d[k%9]. Output flat (B,N,P,324)==(B,N*C,H,W).
// ---------------------------------------------------------------------------
__global__ __launch_bounds__(256) void gather_kernel(const float* __restrict__ coords,
                                                     float* __restrict__ out) {
    const int idx = blockIdx.x * 256 + threadIdx.x;    // exact: no bounds needed
    const int c   = idx % 324;
    const int bnp = idx / 324;
    const int p  = bnp & 4095;
    const int bn = bnp >> 12;
    const int b  = bn >> 2;

    const float cx = coords[((size_t)bn * 2)     * PQ + p];
    const float cy = coords[((size_t)bn * 2 + 1) * PQ + p];

    const float* pyr = g_pyr + ((((size_t)b << 12) | (size_t)p) * PYR);

    const int l = c / 81;
    const int k = c - l * 81;
    const int dim  = 64 >> l;
    const float inv = 1.0f / (float)(1 << l);
    const int loff = (l == 0) ? 0 : (l == 1) ? 4096 : (l == 2) ? 5120 : 5376;
    const float* lv = pyr + loff;

    const int ki = k / 9;
    const float x = cx * inv + (float)(ki - 4);            // off_x = d[k/9]
    const float y = cy * inv + (float)(k - ki * 9 - 4);    // off_y = d[k%9]

    const float x0f = floorf(x), y0f = floorf(y);
    const int x0 = (int)x0f, y0 = (int)y0f;
    const float fx = x - x0f, fy = y - y0f;

    const bool xv0 = (x0 >= 0) && (x0 < dim);
    const bool xv1 = (x0 >= -1) && (x0 < dim - 1);
    const bool yv0 = (y0 >= 0) && (y0 < dim);
    const bool yv1 = (y0 >= -1) && (y0 < dim - 1);

    float v00 = 0.f, v01 = 0.f, v10 = 0.f, v11 = 0.f;
    const float* row0 = lv + y0 * dim;
    if (yv0) {
        if (xv0) v00 = row0[x0];
        if (xv1) v01 = row0[x0 + 1];
    }
    if (yv1) {
        if (xv0) v10 = row0[dim + x0];
        if (xv1) v11 = row0[dim + x0 + 1];
    }
    out[idx] = (1.f - fy) * ((1.f - fx) * v00 + fx * v01)
             + fy         * ((1.f - fx) * v10 + fx * v11);
}

extern "C" void kernel_launch(void* const* d_in, const int* in_sizes, int n_in,
                              void* d_out, int out_size) {
    const float* f1     = (const float*)d_in[0];   // (2, 256, 64, 64)
    const float* f2     = (const float*)d_in[1];   // (2, 256, 64, 64)
    const float* coords = (const float*)d_in[2];   // (2, 4, 2, 64, 64)
    float* out = (float*)d_out;                    // (2, 4*324, 64, 64)

    dim3 g(32, 32, 2);                             // n-tiles, m-tiles, batch
    gemm_corr<<<g, 128>>>(f1, f2);
    pool23_kernel<<<2 * PQ, 256>>>();
    gather_kernel<<<(2 * 4 * PQ * 324) / 256, 256>>>(coords, out);
}